// round 9
// baseline (speedup 1.0000x reference)
#include <cuda_runtime.h>
#include <cstdint>

// ---------------- problem constants ----------------
#define M_TOTAL 32768          // B*L tokens
#define K_DIM   1536           // H2
#define T_DIM   64             // tags
#define BM      256            // tokens per CTA
#define BK      32             // K per tile
#define NTK     (K_DIM / BK)   // 48 k-tiles
#define GRID    (M_TOTAL / BM) // 128 CTAs (1 per SM, single wave)
#define THREADS 256            // 8 warps: 4 (m) x 2 (n), warp tile 64m x 32n
#define RESCUE_THR 0.03f       // ~16 sigma of 1-term bf16 logit error

// ---------------- dynamic SMEM layout (bytes) ----------------
#define SM_REDF   128                    // 8 floats
#define SM_REDR   192                    // 8 ints
#define SM_REDV   256                    // 8 ints
#define SM_LAST   448                    // int flag
#define SM_BIAS   512                    // 64 floats
#define A_ROW     80
#define A_BUF     (BM * A_ROW)           // 20480
#define W_BUF     (T_DIM * A_ROW)        // 5120
#define A_HI_OFF  1024
#define W_HI_OFF  (A_HI_OFF + 2 * A_BUF) // 41984
// C overlay (after GEMM): [256][65] f32 at offset 1024 -> needs 1024 + 66560
#define SMEM_TOTAL (1024 + BM * 65 * 4)  // 67584

// ---------------- device scratch (no allocs allowed) ----------------
__device__ float    g_part_loss[GRID];
__device__ int      g_part_right[GRID];
__device__ int      g_part_valid[GRID];
__device__ int      g_tag_stride;
__device__ unsigned g_done;              // zero-init; last CTA resets to 0 each run
__device__ unsigned g_whi[NTK * 1024];   // W bf16 tiles, [kt][n=64][k=32] = 1024 uints/tile

// ---------------- helpers ----------------
__device__ __forceinline__ uint32_t smem_u32(const void* p) {
    uint32_t a;
    asm("{ .reg .u64 t; cvta.to.shared.u64 t, %1; cvt.u32.u64 %0, t; }" : "=r"(a) : "l"(p));
    return a;
}
__device__ __forceinline__ unsigned cvt_bf16x2(float a, float b) {
    // result: lo16 = bf16(a), hi16 = bf16(b)
    unsigned r;
    asm("cvt.rn.bf16x2.f32 %0, %1, %2;" : "=r"(r) : "f"(b), "f"(a));
    return r;
}

#define LDMX4(r, addr)                                                          \
    asm volatile("ldmatrix.sync.aligned.m8n8.x4.shared.b16 {%0,%1,%2,%3}, [%4];"\
                 : "=r"((r)[0]), "=r"((r)[1]), "=r"((r)[2]), "=r"((r)[3])       \
                 : "r"(addr))

#define MMA16816(c, a, b0, b1)                                                  \
    asm volatile("mma.sync.aligned.m16n8k16.row.col.f32.bf16.bf16.f32 "         \
                 "{%0,%1,%2,%3}, {%4,%5,%6,%7}, {%8,%9}, {%0,%1,%2,%3};"        \
                 : "+f"((c)[0]), "+f"((c)[1]), "+f"((c)[2]), "+f"((c)[3])       \
                 : "r"((a)[0]), "r"((a)[1]), "r"((a)[2]), "r"((a)[3]),          \
                   "r"(b0), "r"(b1))

// ---------------- prep: W -> bf16 tiles + tag dtype detection ----------------
__global__ void prep_kernel(const float* __restrict__ W,
                            const int* __restrict__ tagw) {
    if (blockIdx.x == 0 && threadIdx.x < 32) {
        int l = threadIdx.x;
        int nz = 0;
#pragma unroll
        for (int i = 0; i < 4; i++) nz |= tagw[2 * (l + 32 * i) + 1];
        unsigned ball = __ballot_sync(0xffffffffu, nz != 0);
        if (l == 0) g_tag_stride = ball ? 1 : 2;
    }

    const int kt  = blockIdx.x;
    const int t   = threadIdx.x;      // 256 threads
    const int n   = t >> 2;           // 0..63 (tag row)
    const int j0  = (t & 3) * 4;      // uint index within 16-uint row
#pragma unroll
    for (int jj = 0; jj < 4; jj++) {
        int j = j0 + jj;              // 0..15 (uint = 2 bf16 along k)
        float v0 = W[(size_t)(kt * BK + 2 * j)     * T_DIM + n];
        float v1 = W[(size_t)(kt * BK + 2 * j + 1) * T_DIM + n];
        g_whi[kt * 1024 + n * 16 + j] = cvt_bf16x2(v0, v1);
    }
}

// ---------------- fused GEMM (1-term bf16) + argmax rescue + loss + finalize ----------------
__global__ __launch_bounds__(THREADS, 1)
void fused_gemm_loss_kernel(const float* __restrict__ x,
                            const float* __restrict__ Wg,
                            const float* __restrict__ bias,
                            const int*   __restrict__ tagw,
                            const float* __restrict__ tts,
                            const int*   __restrict__ tptr,
                            float* __restrict__ out)
{
    extern __shared__ char smem[];
    const uint32_t sb  = smem_u32(smem);
    const int tid  = threadIdx.x;
    const int wid  = tid >> 5;
    const int lane = tid & 31;
    const int wm   = wid >> 1;        // 0..3 (m group of 64 rows)
    const int wn   = wid & 1;         // 0..1 (n group of 32 cols)
    const int m0   = blockIdx.x * BM;

    if (tid < T_DIM) ((float*)(smem + SM_BIAS))[tid] = bias[tid];

    float c[4][4][4];                 // [i: m16 subtile][j: n8 subtile][frag]
#pragma unroll
    for (int i = 0; i < 4; i++)
#pragma unroll
        for (int j = 0; j < 4; j++)
#pragma unroll
            for (int q = 0; q < 4; q++) c[i][j][q] = 0.0f;

    // ---- prefetch tile 0 ----
    // x tile: 256 rows x 32 floats = 2048 float4; 256 threads -> 8 each
    // W tile: 512 uint2; 256 threads -> 2 each
    float4 xv[8]; uint2 whv[2];
    {
#pragma unroll
        for (int i = 0; i < 8; i++) {
            int lin = i * THREADS + tid;
            int row = lin >> 3, c4 = lin & 7;
            xv[i] = *(const float4*)(x + (size_t)(m0 + row) * K_DIM + c4 * 4);
        }
        whv[0] = ((const uint2*)g_whi)[tid];
        whv[1] = ((const uint2*)g_whi)[tid + 256];
    }

    auto store_tile = [&](int b, const float4 xr[8], const uint2 wh[2]) {
        char* ah = smem + A_HI_OFF + b * A_BUF;
#pragma unroll
        for (int i = 0; i < 8; i++) {
            int lin = i * THREADS + tid;
            int row = lin >> 3, c4 = lin & 7;
            float4 f = xr[i];
            unsigned h01 = cvt_bf16x2(f.x, f.y);
            unsigned h23 = cvt_bf16x2(f.z, f.w);
            *(uint2*)(ah + row * A_ROW + c4 * 8) = make_uint2(h01, h23);
        }
#pragma unroll
        for (int i = 0; i < 2; i++) {
            int idx = i * THREADS + tid;          // 512 uint2: 64 rows x 8 uint2
            int n = idx >> 3, j2 = (idx & 7) * 8;
            *(uint2*)(smem + W_HI_OFF + b * W_BUF + n * A_ROW + j2) = wh[i];
        }
    };

    store_tile(0, xv, whv);
    __syncthreads();

    const int quad = lane >> 3, r8 = lane & 7;

    for (int kt = 0; kt < NTK; kt++) {
        const int b = kt & 1;

        // prefetch next tile (LDG early, hidden under MMA)
        if (kt + 1 < NTK) {
            const int k0 = (kt + 1) * BK;
#pragma unroll
            for (int i = 0; i < 8; i++) {
                int lin = i * THREADS + tid;
                int row = lin >> 3, c4 = lin & 7;
                xv[i] = *(const float4*)(x + (size_t)(m0 + row) * K_DIM + k0 + c4 * 4);
            }
            whv[0] = ((const uint2*)g_whi)[(kt + 1) * 512 + tid];
            whv[1] = ((const uint2*)g_whi)[(kt + 1) * 512 + tid + 256];
        }

        // ---- compute on buffer b ----
        const uint32_t aH = sb + A_HI_OFF + b * A_BUF;
        const uint32_t wH = sb + W_HI_OFF + b * W_BUF;

#pragma unroll
        for (int kk = 0; kk < 2; kk++) {
            unsigned bh[8];
            const int nB = wn * 32 + ((quad >> 1) << 3) + r8;
            const int kB = kk * 16 + ((quad & 1) << 3);
#pragma unroll
            for (int s = 0; s < 2; s++) {
                uint32_t off = (uint32_t)(nB + s * 16) * A_ROW + kB * 2;
                LDMX4(&bh[s * 4], wH + off);
            }
            const int kA = kk * 16 + ((quad >> 1) << 3);
#pragma unroll
            for (int i = 0; i < 4; i++) {
                unsigned ah[4];
                const int mA = wm * 64 + i * 16 + ((quad & 1) << 3) + r8;
                uint32_t off = (uint32_t)mA * A_ROW + kA * 2;
                LDMX4(ah, aH + off);
#pragma unroll
                for (int j = 0; j < 4; j++)
                    MMA16816(c[i][j], ah, bh[2 * j], bh[2 * j + 1]);
            }
        }

        if (kt + 1 < NTK) store_tile(b ^ 1, xv, whv);
        __syncthreads();
    }

    // ---- write C fragments to smem [256][65] f32 ----
    float* cs = (float*)(smem + A_HI_OFF);
    const int g = lane >> 2, tg = lane & 3;
#pragma unroll
    for (int i = 0; i < 4; i++)
#pragma unroll
        for (int j = 0; j < 4; j++) {
            int row = wm * 64 + i * 16 + g;
            int col = wn * 32 + j * 8 + tg * 2;
            cs[row * 65 + col]           = c[i][j][0];
            cs[row * 65 + col + 1]       = c[i][j][1];
            cs[(row + 8) * 65 + col]     = c[i][j][2];
            cs[(row + 8) * 65 + col + 1] = c[i][j][3];
        }
    __syncthreads();

    // ---- per-token stats (one token per thread) ----
    const float* biass = (const float*)(smem + SM_BIAS);
    const int token = m0 + tid;
    const int tag = (g_tag_stride == 2) ? tagw[2 * token] : tagw[token];
    const float* row = cs + tid * 65;

    float mv = -3.4e38f; int mi = 0;
    float sl = 0.0f, st = 0.0f;
#pragma unroll
    for (int cc = 0; cc < T_DIM; cc++) {
        float vv = row[cc] + biass[cc];
        sl += vv;
        if (vv > mv) { mv = vv; mi = cc; }
        if (cc == tag) st = vv;
    }
    float se = 0.0f;
    float m2 = -3.4e38f;
#pragma unroll
    for (int cc = 0; cc < T_DIM; cc++) {
        float vv = row[cc] + biass[cc];
        se += expf(vv - mv);
        if (cc != mi && vv > m2) m2 = vv;
    }

    // ---- argmax rescue: exact fp32 recompute for near-ties ----
    bool rescue = (mv - m2) < RESCUE_THR;
    int ncand = 0; unsigned p0 = 0, p1 = 0;
    if (rescue) {
#pragma unroll
        for (int cc = 0; cc < T_DIM; cc++) {
            float vv = row[cc] + biass[cc];
            if (vv >= mv - RESCUE_THR && ncand < 8) {
                if (ncand < 4) p0 |= (unsigned)cc << (8 * ncand);
                else           p1 |= (unsigned)cc << (8 * (ncand - 4));
                ncand++;
            }
        }
    }
    unsigned need = __ballot_sync(0xffffffffu, rescue);
    while (need) {
        int src = __ffs(need) - 1;
        need &= need - 1;
        int      nc = __shfl_sync(0xffffffffu, ncand, src);
        unsigned q0 = __shfl_sync(0xffffffffu, p0, src);
        unsigned q1 = __shfl_sync(0xffffffffu, p1, src);
        int cidx[8];
#pragma unroll
        for (int j = 0; j < 8; j++)
            cidx[j] = (int)((j < 4 ? (q0 >> (8 * j)) : (q1 >> (8 * (j - 4)))) & 0xffu);

        const float* xr = x + (size_t)(m0 + (wid << 5) + src) * K_DIM;
        float acc[8];
#pragma unroll
        for (int j = 0; j < 8; j++) acc[j] = 0.0f;
#pragma unroll 4
        for (int i = 0; i < K_DIM / 32; i++) {
            int k = lane + 32 * i;                // coalesced
            float xvv = xr[k];
#pragma unroll
            for (int j = 0; j < 8; j++)
                if (j < nc) acc[j] += xvv * Wg[(size_t)k * T_DIM + cidx[j]];
        }
#pragma unroll
        for (int j = 0; j < 8; j++)
#pragma unroll
            for (int off = 16; off > 0; off >>= 1)
                acc[j] += __shfl_xor_sync(0xffffffffu, acc[j], off);
        // candidates ascending -> strict '>' keeps smallest-index tie-break
        float bmv = -3.4e38f; int bmi = 0;
#pragma unroll
        for (int j = 0; j < 8; j++)
            if (j < nc) {
                float vv = acc[j] + biass[cidx[j]];
                if (vv > bmv) { bmv = vv; bmi = cidx[j]; }
            }
        if (lane == src) mi = bmi;
    }

    // ---- loss ----
    const float E1 = 2.718281828459045f;
    float LSE = mv + logf(se);
    int   traw = *tptr;
    float tf = (traw > -1000000 && traw < 1000000) ? (float)traw : __int_as_float(traw);
    float s  = powf(tts[tag], tf);
    float es = expf(s);
    float Z  = 63.0f * E1 + es;
    float thr_loss  = LSE - ((E1 / Z) * (sl - st) + (es / Z) * st);
    int   thr_valid = (tag < (T_DIM - 3)) ? 1 : 0;
    int   thr_right = (thr_valid && (mi == tag)) ? 1 : 0;

    // ---- deterministic block reduction (8 warps) ----
    float* s_loss  = (float*)(smem + SM_REDF);
    int*   s_right = (int*)(smem + SM_REDR);
    int*   s_valid = (int*)(smem + SM_REDV);
    int*   s_last  = (int*)(smem + SM_LAST);
#pragma unroll
    for (int off = 16; off > 0; off >>= 1) {
        thr_loss  += __shfl_xor_sync(0xffffffffu, thr_loss,  off);
        thr_right += __shfl_xor_sync(0xffffffffu, thr_right, off);
        thr_valid += __shfl_xor_sync(0xffffffffu, thr_valid, off);
    }
    if (lane == 0) { s_loss[wid] = thr_loss; s_right[wid] = thr_right; s_valid[wid] = thr_valid; }
    __syncthreads();
    if (tid == 0) {
        float L = 0.0f; int R = 0, V = 0;
        for (int w = 0; w < 8; w++) { L += s_loss[w]; R += s_right[w]; V += s_valid[w]; }
        g_part_loss[blockIdx.x]  = L;
        g_part_right[blockIdx.x] = R;
        g_part_valid[blockIdx.x] = V;
        __threadfence();
        unsigned prev = atomicAdd(&g_done, 1u);
        *s_last = (prev == GRID - 1) ? 1 : 0;
    }
    __syncthreads();

    // ---- last CTA: deterministic global reduction + output ----
    if (*s_last) {
        __threadfence();   // acquire all partials
        float L = 0.0f; int R = 0, V = 0;
        if (tid < GRID) {  // GRID == 128 -> warps 0..3
            L = g_part_loss[tid];
            R = g_part_right[tid];
            V = g_part_valid[tid];
        }
#pragma unroll
        for (int off = 16; off > 0; off >>= 1) {
            L += __shfl_xor_sync(0xffffffffu, L, off);
            R += __shfl_xor_sync(0xffffffffu, R, off);
            V += __shfl_xor_sync(0xffffffffu, V, off);
        }
        if (lane == 0) { s_loss[wid] = L; s_right[wid] = R; s_valid[wid] = V; }
        __syncthreads();
        if (tid == 0) {
            double LT = 0.0; long long RT = 0, VT = 0;
            for (int w = 0; w < 4; w++) {
                LT += (double)s_loss[w]; RT += s_right[w]; VT += s_valid[w];
            }
            out[0] = (float)LT;
            out[1] = (float)((double)RT / (double)VT);
            atomicExch(&g_done, 0u);   // reset for next graph replay
        }
    }
}

extern "C" void kernel_launch(void* const* d_in, const int* in_sizes, int n_in,
                              void* d_out, int out_size) {
    const float* x    = (const float*)d_in[0];
    const float* W    = (const float*)d_in[1];
    const float* b    = (const float*)d_in[2];
    const int*   tagw = (const int*)d_in[3];   // raw 32-bit view, dtype detected on device
    // d_in[4] = attention_mask: uniform additive shift over tag dim -> provably a no-op
    const float* tts  = (const float*)d_in[5];
    const int*   tptr = (const int*)d_in[6];

    static int smem_set = 0;
    if (!smem_set) {
        cudaFuncSetAttribute(fused_gemm_loss_kernel,
                             cudaFuncAttributeMaxDynamicSharedMemorySize, SMEM_TOTAL);
        smem_set = 1;
    }

    prep_kernel<<<NTK, 256>>>(W, tagw);
    fused_gemm_loss_kernel<<<GRID, THREADS, SMEM_TOTAL>>>(x, W, b, tagw, tts, tptr,
                                                          (float*)d_out);
}

// round 10
// speedup vs baseline: 1.2622x; 1.2622x over previous
#include <cuda_runtime.h>
#include <cstdint>

// ---------------- problem constants ----------------
#define M_TOTAL 32768          // B*L tokens
#define K_DIM   1536           // H2
#define T_DIM   64             // tags
#define BM      256            // tokens per CTA
#define BK      32             // K per tile
#define NTK     (K_DIM / BK)   // 48 k-tiles
#define GRID    (M_TOTAL / BM) // 128 CTAs (1 per SM, single wave)
#define THREADS 256            // 8 warps: 4 (m) x 2 (n), warp tile 64m x 32n
#define RESCUE_THR 0.03f       // ~16 sigma of 1-term bf16 logit error
#define RGRID   128            // rescue kernel CTAs

// ---------------- dynamic SMEM layout (bytes) ----------------
#define SM_REDF   128                    // 8 floats
#define SM_REDR   192                    // 8 ints
#define SM_REDV   256                    // 8 ints
#define SM_LAST   448                    // int flag
#define SM_BIAS   512                    // 64 floats
#define A_ROW     80
#define A_BUF     (BM * A_ROW)           // 20480
#define W_BUF     (T_DIM * A_ROW)        // 5120
#define A_HI_OFF  1024
#define W_HI_OFF  (A_HI_OFF + 2 * A_BUF) // 41984
// C overlay (after GEMM): [256][65] f32 at offset 1024 -> needs 1024 + 66560
#define SMEM_TOTAL (1024 + BM * 65 * 4)  // 67584

// ---------------- device scratch (no allocs allowed) ----------------
__device__ float    g_part_loss[GRID];
__device__ int      g_part_right[GRID];
__device__ int      g_part_valid[GRID];
__device__ int      g_tag_stride;
__device__ unsigned g_nwork;             // worklist size (reset by rescue last CTA)
__device__ unsigned g_done2;             // rescue completion counter
__device__ int      g_right_corr;        // argmax corrections (summed ints)
__device__ int4     g_work[M_TOTAL];     // worklist entries
__device__ unsigned g_whi[NTK * 1024];   // W bf16 tiles, [kt][n=64][k=32] = 1024 uints/tile

// ---------------- helpers ----------------
__device__ __forceinline__ uint32_t smem_u32(const void* p) {
    uint32_t a;
    asm("{ .reg .u64 t; cvta.to.shared.u64 t, %1; cvt.u32.u64 %0, t; }" : "=r"(a) : "l"(p));
    return a;
}
__device__ __forceinline__ unsigned cvt_bf16x2(float a, float b) {
    // result: lo16 = bf16(a), hi16 = bf16(b)
    unsigned r;
    asm("cvt.rn.bf16x2.f32 %0, %1, %2;" : "=r"(r) : "f"(b), "f"(a));
    return r;
}

#define LDMX4(r, addr)                                                          \
    asm volatile("ldmatrix.sync.aligned.m8n8.x4.shared.b16 {%0,%1,%2,%3}, [%4];"\
                 : "=r"((r)[0]), "=r"((r)[1]), "=r"((r)[2]), "=r"((r)[3])       \
                 : "r"(addr))

#define MMA16816(c, a, b0, b1)                                                  \
    asm volatile("mma.sync.aligned.m16n8k16.row.col.f32.bf16.bf16.f32 "         \
                 "{%0,%1,%2,%3}, {%4,%5,%6,%7}, {%8,%9}, {%0,%1,%2,%3};"        \
                 : "+f"((c)[0]), "+f"((c)[1]), "+f"((c)[2]), "+f"((c)[3])       \
                 : "r"((a)[0]), "r"((a)[1]), "r"((a)[2]), "r"((a)[3]),          \
                   "r"(b0), "r"(b1))

// ---------------- prep: W -> bf16 tiles + tag dtype detection ----------------
__global__ void prep_kernel(const float* __restrict__ W,
                            const int* __restrict__ tagw) {
    if (blockIdx.x == 0 && threadIdx.x < 32) {
        int l = threadIdx.x;
        int nz = 0;
#pragma unroll
        for (int i = 0; i < 4; i++) nz |= tagw[2 * (l + 32 * i) + 1];
        unsigned ball = __ballot_sync(0xffffffffu, nz != 0);
        if (l == 0) g_tag_stride = ball ? 1 : 2;
    }

    const int kt  = blockIdx.x;
    const int t   = threadIdx.x;      // 256 threads
    const int n   = t >> 2;           // 0..63 (tag row)
    const int j0  = (t & 3) * 4;      // uint index within 16-uint row
#pragma unroll
    for (int jj = 0; jj < 4; jj++) {
        int j = j0 + jj;              // 0..15 (uint = 2 bf16 along k)
        float v0 = W[(size_t)(kt * BK + 2 * j)     * T_DIM + n];
        float v1 = W[(size_t)(kt * BK + 2 * j + 1) * T_DIM + n];
        g_whi[kt * 1024 + n * 16 + j] = cvt_bf16x2(v0, v1);
    }
}

// ---------------- fused GEMM (1-term bf16) + loss + worklist emit ----------------
__global__ __launch_bounds__(THREADS, 1)
void fused_gemm_loss_kernel(const float* __restrict__ x,
                            const float* __restrict__ bias,
                            const int*   __restrict__ tagw,
                            const float* __restrict__ tts,
                            const int*   __restrict__ tptr)
{
    extern __shared__ char smem[];
    const uint32_t sb  = smem_u32(smem);
    const int tid  = threadIdx.x;
    const int wid  = tid >> 5;
    const int lane = tid & 31;
    const int wm   = wid >> 1;        // 0..3 (m group of 64 rows)
    const int wn   = wid & 1;         // 0..1 (n group of 32 cols)
    const int m0   = blockIdx.x * BM;

    if (tid < T_DIM) ((float*)(smem + SM_BIAS))[tid] = bias[tid];

    float c[4][4][4];                 // [i: m16 subtile][j: n8 subtile][frag]
#pragma unroll
    for (int i = 0; i < 4; i++)
#pragma unroll
        for (int j = 0; j < 4; j++)
#pragma unroll
            for (int q = 0; q < 4; q++) c[i][j][q] = 0.0f;

    // ---- prefetch tile 0 ----
    float4 xv[8]; uint2 whv[2];
    {
#pragma unroll
        for (int i = 0; i < 8; i++) {
            int lin = i * THREADS + tid;
            int row = lin >> 3, c4 = lin & 7;
            xv[i] = *(const float4*)(x + (size_t)(m0 + row) * K_DIM + c4 * 4);
        }
        whv[0] = ((const uint2*)g_whi)[tid];
        whv[1] = ((const uint2*)g_whi)[tid + 256];
    }

    auto store_tile = [&](int b, const float4 xr[8], const uint2 wh[2]) {
        char* ah = smem + A_HI_OFF + b * A_BUF;
#pragma unroll
        for (int i = 0; i < 8; i++) {
            int lin = i * THREADS + tid;
            int row = lin >> 3, c4 = lin & 7;
            float4 f = xr[i];
            unsigned h01 = cvt_bf16x2(f.x, f.y);
            unsigned h23 = cvt_bf16x2(f.z, f.w);
            *(uint2*)(ah + row * A_ROW + c4 * 8) = make_uint2(h01, h23);
        }
#pragma unroll
        for (int i = 0; i < 2; i++) {
            int idx = i * THREADS + tid;          // 512 uint2: 64 rows x 8 uint2
            int n = idx >> 3, j2 = (idx & 7) * 8;
            *(uint2*)(smem + W_HI_OFF + b * W_BUF + n * A_ROW + j2) = wh[i];
        }
    };

    store_tile(0, xv, whv);
    __syncthreads();

    const int quad = lane >> 3, r8 = lane & 7;

    for (int kt = 0; kt < NTK; kt++) {
        const int b = kt & 1;

        if (kt + 1 < NTK) {
            const int k0 = (kt + 1) * BK;
#pragma unroll
            for (int i = 0; i < 8; i++) {
                int lin = i * THREADS + tid;
                int row = lin >> 3, c4 = lin & 7;
                xv[i] = *(const float4*)(x + (size_t)(m0 + row) * K_DIM + k0 + c4 * 4);
            }
            whv[0] = ((const uint2*)g_whi)[(kt + 1) * 512 + tid];
            whv[1] = ((const uint2*)g_whi)[(kt + 1) * 512 + tid + 256];
        }

        const uint32_t aH = sb + A_HI_OFF + b * A_BUF;
        const uint32_t wH = sb + W_HI_OFF + b * W_BUF;

#pragma unroll
        for (int kk = 0; kk < 2; kk++) {
            unsigned bh[8];
            const int nB = wn * 32 + ((quad >> 1) << 3) + r8;
            const int kB = kk * 16 + ((quad & 1) << 3);
#pragma unroll
            for (int s = 0; s < 2; s++) {
                uint32_t off = (uint32_t)(nB + s * 16) * A_ROW + kB * 2;
                LDMX4(&bh[s * 4], wH + off);
            }
            const int kA = kk * 16 + ((quad >> 1) << 3);
#pragma unroll
            for (int i = 0; i < 4; i++) {
                unsigned ah[4];
                const int mA = wm * 64 + i * 16 + ((quad & 1) << 3) + r8;
                uint32_t off = (uint32_t)mA * A_ROW + kA * 2;
                LDMX4(ah, aH + off);
#pragma unroll
                for (int j = 0; j < 4; j++)
                    MMA16816(c[i][j], ah, bh[2 * j], bh[2 * j + 1]);
            }
        }

        if (kt + 1 < NTK) store_tile(b ^ 1, xv, whv);
        __syncthreads();
    }

    // ---- write C fragments to smem [256][65] f32 ----
    float* cs = (float*)(smem + A_HI_OFF);
    const int g = lane >> 2, tg = lane & 3;
#pragma unroll
    for (int i = 0; i < 4; i++)
#pragma unroll
        for (int j = 0; j < 4; j++) {
            int row = wm * 64 + i * 16 + g;
            int col = wn * 32 + j * 8 + tg * 2;
            cs[row * 65 + col]           = c[i][j][0];
            cs[row * 65 + col + 1]       = c[i][j][1];
            cs[(row + 8) * 65 + col]     = c[i][j][2];
            cs[(row + 8) * 65 + col + 1] = c[i][j][3];
        }
    __syncthreads();

    // ---- per-token stats (one token per thread) ----
    const float* biass = (const float*)(smem + SM_BIAS);
    const int token = m0 + tid;
    const int tag = (g_tag_stride == 2) ? tagw[2 * token] : tagw[token];
    const float* row = cs + tid * 65;

    float mv = -3.4e38f; int mi = 0;
    float sl = 0.0f, st = 0.0f;
#pragma unroll
    for (int cc = 0; cc < T_DIM; cc++) {
        float vv = row[cc] + biass[cc];
        sl += vv;
        if (vv > mv) { mv = vv; mi = cc; }
        if (cc == tag) st = vv;
    }
    float se = 0.0f;
    float m2 = -3.4e38f;
#pragma unroll
    for (int cc = 0; cc < T_DIM; cc++) {
        float vv = row[cc] + biass[cc];
        se += expf(vv - mv);
        if (cc != mi && vv > m2) m2 = vv;
    }

    // ---- loss (bf16-accuracy logits; unbiased rounding -> rel err ~1e-6) ----
    const float E1 = 2.718281828459045f;
    float LSE = mv + logf(se);
    int   traw = *tptr;
    float tf = (traw > -1000000 && traw < 1000000) ? (float)traw : __int_as_float(traw);
    float s  = powf(tts[tag], tf);
    float es = expf(s);
    float Z  = 63.0f * E1 + es;
    float thr_loss  = LSE - ((E1 / Z) * (sl - st) + (es / Z) * st);
    int   thr_valid = (tag < (T_DIM - 3)) ? 1 : 0;
    int   thr_right = (thr_valid && (mi == tag)) ? 1 : 0;

    // ---- emit near-tie tokens to rescue worklist (no recompute here) ----
    if (mv - m2 < RESCUE_THR) {
        int ncand = 0; unsigned p0 = 0, p1 = 0;
#pragma unroll
        for (int cc = 0; cc < T_DIM; cc++) {
            float vv = row[cc] + biass[cc];
            if (vv >= mv - RESCUE_THR && ncand < 8) {
                if (ncand < 4) p0 |= (unsigned)cc << (8 * ncand);
                else           p1 |= (unsigned)cc << (8 * (ncand - 4));
                ncand++;
            }
        }
        unsigned slot = atomicAdd(&g_nwork, 1u);
        int meta = ncand | (tag << 4) | (thr_right << 12) | (thr_valid << 13);
        g_work[slot] = make_int4(token, meta, (int)p0, (int)p1);
    }

    // ---- deterministic block reduction (8 warps) -> partials ----
    float* s_loss  = (float*)(smem + SM_REDF);
    int*   s_right = (int*)(smem + SM_REDR);
    int*   s_valid = (int*)(smem + SM_REDV);
#pragma unroll
    for (int off = 16; off > 0; off >>= 1) {
        thr_loss  += __shfl_xor_sync(0xffffffffu, thr_loss,  off);
        thr_right += __shfl_xor_sync(0xffffffffu, thr_right, off);
        thr_valid += __shfl_xor_sync(0xffffffffu, thr_valid, off);
    }
    if (lane == 0) { s_loss[wid] = thr_loss; s_right[wid] = thr_right; s_valid[wid] = thr_valid; }
    __syncthreads();
    if (tid == 0) {
        float L = 0.0f; int R = 0, V = 0;
        for (int w = 0; w < 8; w++) { L += s_loss[w]; R += s_right[w]; V += s_valid[w]; }
        g_part_loss[blockIdx.x]  = L;
        g_part_right[blockIdx.x] = R;
        g_part_valid[blockIdx.x] = V;
    }
}

// ---------------- rescue: exact fp32 argmax for near-tie tokens + finalize ----------------
__global__ __launch_bounds__(256, 1)
void rescue_kernel(const float* __restrict__ x,
                   const float* __restrict__ Wg,
                   const float* __restrict__ bias,
                   float* __restrict__ out)
{
    __shared__ float s_loss[8];
    __shared__ int   s_right[8];
    __shared__ int   s_valid[8];
    __shared__ int   s_last;

    const int tid  = threadIdx.x;
    const int wid  = tid >> 5;
    const int lane = tid & 31;
    const unsigned nwork = g_nwork;
    const int gw = blockIdx.x * 8 + wid;          // global warp id (0..1023)

    for (unsigned e = gw; e < nwork; e += RGRID * 8) {
        int4 ent = g_work[e];
        const int token = ent.x;
        const int nc    = ent.y & 15;
        const int tag   = (ent.y >> 4) & 63;
        const int oldr  = (ent.y >> 12) & 1;
        const int valid = (ent.y >> 13) & 1;
        const unsigned q0 = (unsigned)ent.z, q1 = (unsigned)ent.w;
        int cidx[8];
#pragma unroll
        for (int j = 0; j < 8; j++)
            cidx[j] = (int)((j < 4 ? (q0 >> (8 * j)) : (q1 >> (8 * (j - 4)))) & 0xffu);

        const float* xr = x + (size_t)token * K_DIM;
        float acc[8];
#pragma unroll
        for (int j = 0; j < 8; j++) acc[j] = 0.0f;
        for (int i = 0; i < K_DIM / 32; i++) {
            int k = lane + 32 * i;                // coalesced
            float xvv = xr[k];
#pragma unroll
            for (int j = 0; j < 8; j++)
                if (j < nc) acc[j] += xvv * Wg[(size_t)k * T_DIM + cidx[j]];
        }
#pragma unroll
        for (int j = 0; j < 8; j++)
#pragma unroll
            for (int off = 16; off > 0; off >>= 1)
                acc[j] += __shfl_xor_sync(0xffffffffu, acc[j], off);

        if (lane == 0 && valid) {
            // candidates ascending -> strict '>' keeps smallest-index tie-break
            float bmv = -3.4e38f; int bmi = 0;
#pragma unroll
            for (int j = 0; j < 8; j++)
                if (j < nc) {
                    float vv = acc[j] + bias[cidx[j]];
                    if (vv > bmv) { bmv = vv; bmi = cidx[j]; }
                }
            int corr = (bmi == tag ? 1 : 0) - oldr;
            if (corr) atomicAdd(&g_right_corr, corr);
        }
    }

    // ---- completion + finalize in last CTA ----
    __syncthreads();
    if (tid == 0) {
        __threadfence();
        unsigned prev = atomicAdd(&g_done2, 1u);
        s_last = (prev == RGRID - 1) ? 1 : 0;
    }
    __syncthreads();
    if (s_last) {
        __threadfence();
        float L = 0.0f; int R = 0, V = 0;
        if (tid < GRID) {                          // GRID == 128
            L = g_part_loss[tid];
            R = g_part_right[tid];
            V = g_part_valid[tid];
        }
#pragma unroll
        for (int off = 16; off > 0; off >>= 1) {
            L += __shfl_xor_sync(0xffffffffu, L, off);
            R += __shfl_xor_sync(0xffffffffu, R, off);
            V += __shfl_xor_sync(0xffffffffu, V, off);
        }
        if (lane == 0) { s_loss[wid] = L; s_right[wid] = R; s_valid[wid] = V; }
        __syncthreads();
        if (tid == 0) {
            double LT = 0.0; long long RT = 0, VT = 0;
            for (int w = 0; w < 4; w++) {
                LT += (double)s_loss[w]; RT += s_right[w]; VT += s_valid[w];
            }
            RT += g_right_corr;
            out[0] = (float)LT;
            out[1] = (float)((double)RT / (double)VT);
            // reset counters for next graph replay
            g_right_corr = 0;
            atomicExch(&g_nwork, 0u);
            atomicExch(&g_done2, 0u);
        }
    }
}

extern "C" void kernel_launch(void* const* d_in, const int* in_sizes, int n_in,
                              void* d_out, int out_size) {
    const float* x    = (const float*)d_in[0];
    const float* W    = (const float*)d_in[1];
    const float* b    = (const float*)d_in[2];
    const int*   tagw = (const int*)d_in[3];   // raw 32-bit view, dtype detected on device
    // d_in[4] = attention_mask: uniform additive shift over tag dim -> provably a no-op
    const float* tts  = (const float*)d_in[5];
    const int*   tptr = (const int*)d_in[6];

    static int smem_set = 0;
    if (!smem_set) {
        cudaFuncSetAttribute(fused_gemm_loss_kernel,
                             cudaFuncAttributeMaxDynamicSharedMemorySize, SMEM_TOTAL);
        smem_set = 1;
    }

    prep_kernel<<<NTK, 256>>>(W, tagw);
    fused_gemm_loss_kernel<<<GRID, THREADS, SMEM_TOTAL>>>(x, b, tagw, tts, tptr);
    rescue_kernel<<<RGRID, 256>>>(x, W, b, (float*)d_out);
}

// round 12
// speedup vs baseline: 2.0438x; 1.6192x over previous
#include <cuda_runtime.h>
#include <cstdint>

// ---------------- problem constants ----------------
#define M_TOTAL 32768          // B*L tokens
#define K_DIM   1536           // H2
#define T_DIM   64             // tags
#define BM      256            // tokens per CTA
#define BK      32             // K per tile
#define NTK     (K_DIM / BK)   // 48 k-tiles
#define GRID    (M_TOTAL / BM) // 128 CTAs (1 per SM, single wave)
#define THREADS 256            // 8 warps: 4 (m) x 2 (n), warp tile 64m x 32n
#define RESCUE_THR 0.03f       // ~16 sigma of 1-term bf16 logit error
#define RGRID   128            // rescue kernel CTAs

// ---------------- dynamic SMEM layout (bytes) ----------------
#define SM_REDF   128                    // 8 floats
#define SM_REDR   192                    // 8 ints
#define SM_REDV   256                    // 8 ints
#define SM_BIAS   512                    // 64 floats
#define A_ROW     80
#define A_BUF     (BM * A_ROW)           // 20480
#define W_BUF     (T_DIM * A_ROW)        // 5120
#define A_HI_OFF  1024
#define W_HI_OFF  (A_HI_OFF + 2 * A_BUF) // 41984
// C overlay (after GEMM): [256][65] f32 at offset 1024 -> needs 1024 + 66560
#define SMEM_TOTAL (1024 + BM * 65 * 4)  // 67584

// ---------------- device scratch (no allocs allowed) ----------------
__device__ float    g_part_loss[GRID];
__device__ int      g_part_right[GRID];
__device__ int      g_part_valid[GRID];
__device__ int      g_tag_stride;
__device__ unsigned g_nwork;             // worklist size (reset by rescue last CTA)
__device__ unsigned g_done2;             // rescue completion counter
__device__ int      g_right_corr;        // argmax corrections (summed ints)
__device__ int4     g_work[M_TOTAL];     // worklist entries
__device__ unsigned g_whi[NTK * 1024];   // W bf16 tiles, [kt][n=64][k=32] = 1024 uints/tile
__device__ float    g_wt[T_DIM * K_DIM]; // fp32 W transpose [tag][k] for coalesced rescue

// ---------------- helpers ----------------
__device__ __forceinline__ uint32_t smem_u32(const void* p) {
    uint32_t a;
    asm("{ .reg .u64 t; cvta.to.shared.u64 t, %1; cvt.u32.u64 %0, t; }" : "=r"(a) : "l"(p));
    return a;
}
__device__ __forceinline__ unsigned cvt_bf16x2(float a, float b) {
    // result: lo16 = bf16(a), hi16 = bf16(b)
    unsigned r;
    asm("cvt.rn.bf16x2.f32 %0, %1, %2;" : "=r"(r) : "f"(b), "f"(a));
    return r;
}

#define LDMX4(r, addr)                                                          \
    asm volatile("ldmatrix.sync.aligned.m8n8.x4.shared.b16 {%0,%1,%2,%3}, [%4];"\
                 : "=r"((r)[0]), "=r"((r)[1]), "=r"((r)[2]), "=r"((r)[3])       \
                 : "r"(addr))

#define MMA16816(c, a, b0, b1)                                                  \
    asm volatile("mma.sync.aligned.m16n8k16.row.col.f32.bf16.bf16.f32 "         \
                 "{%0,%1,%2,%3}, {%4,%5,%6,%7}, {%8,%9}, {%0,%1,%2,%3};"        \
                 : "+f"((c)[0]), "+f"((c)[1]), "+f"((c)[2]), "+f"((c)[3])       \
                 : "r"((a)[0]), "r"((a)[1]), "r"((a)[2]), "r"((a)[3]),          \
                   "r"(b0), "r"(b1))

// ---------------- prep: W -> bf16 tiles + fp32 transpose + tag dtype detection ----------------
__global__ void prep_kernel(const float* __restrict__ W,
                            const int* __restrict__ tagw) {
    if (blockIdx.x == 0 && threadIdx.x < 32) {
        int l = threadIdx.x;
        int nz = 0;
#pragma unroll
        for (int i = 0; i < 4; i++) nz |= tagw[2 * (l + 32 * i) + 1];
        unsigned ball = __ballot_sync(0xffffffffu, nz != 0);
        if (l == 0) g_tag_stride = ball ? 1 : 2;
    }

    const int kt  = blockIdx.x;
    const int t   = threadIdx.x;      // 256 threads
    const int n   = t >> 2;           // 0..63 (tag row)
    const int j0  = (t & 3) * 4;      // uint index within 16-uint row
#pragma unroll
    for (int jj = 0; jj < 4; jj++) {
        int j = j0 + jj;              // 0..15 (uint = 2 bf16 along k)
        int k0 = kt * BK + 2 * j;
        float v0 = W[(size_t)k0       * T_DIM + n];
        float v1 = W[(size_t)(k0 + 1) * T_DIM + n];
        g_whi[kt * 1024 + n * 16 + j] = cvt_bf16x2(v0, v1);
        g_wt[(size_t)n * K_DIM + k0]     = v0;   // fp32 transpose for rescue
        g_wt[(size_t)n * K_DIM + k0 + 1] = v1;
    }
}

// ---------------- fused GEMM (1-term bf16) + loss + worklist emit ----------------
__global__ __launch_bounds__(THREADS, 1)
void fused_gemm_loss_kernel(const float* __restrict__ x,
                            const float* __restrict__ bias,
                            const int*   __restrict__ tagw,
                            const float* __restrict__ tts,
                            const int*   __restrict__ tptr)
{
    extern __shared__ char smem[];
    const uint32_t sb  = smem_u32(smem);
    const int tid  = threadIdx.x;
    const int wid  = tid >> 5;
    const int lane = tid & 31;
    const int wm   = wid >> 1;        // 0..3 (m group of 64 rows)
    const int wn   = wid & 1;         // 0..1 (n group of 32 cols)
    const int m0   = blockIdx.x * BM;

    if (tid < T_DIM) ((float*)(smem + SM_BIAS))[tid] = bias[tid];

    float c[4][4][4];                 // [i: m16 subtile][j: n8 subtile][frag]
#pragma unroll
    for (int i = 0; i < 4; i++)
#pragma unroll
        for (int j = 0; j < 4; j++)
#pragma unroll
            for (int q = 0; q < 4; q++) c[i][j][q] = 0.0f;

    // ---- prefetch tile 0 ----
    float4 xv[8]; uint2 whv[2];
    {
#pragma unroll
        for (int i = 0; i < 8; i++) {
            int lin = i * THREADS + tid;
            int row = lin >> 3, c4 = lin & 7;
            xv[i] = *(const float4*)(x + (size_t)(m0 + row) * K_DIM + c4 * 4);
        }
        whv[0] = ((const uint2*)g_whi)[tid];
        whv[1] = ((const uint2*)g_whi)[tid + 256];
    }

    auto store_tile = [&](int b, const float4 xr[8], const uint2 wh[2]) {
        char* ah = smem + A_HI_OFF + b * A_BUF;
#pragma unroll
        for (int i = 0; i < 8; i++) {
            int lin = i * THREADS + tid;
            int row = lin >> 3, c4 = lin & 7;
            float4 f = xr[i];
            unsigned h01 = cvt_bf16x2(f.x, f.y);
            unsigned h23 = cvt_bf16x2(f.z, f.w);
            *(uint2*)(ah + row * A_ROW + c4 * 8) = make_uint2(h01, h23);
        }
#pragma unroll
        for (int i = 0; i < 2; i++) {
            int idx = i * THREADS + tid;          // 512 uint2: 64 rows x 8 uint2
            int n = idx >> 3, j2 = (idx & 7) * 8;
            *(uint2*)(smem + W_HI_OFF + b * W_BUF + n * A_ROW + j2) = wh[i];
        }
    };

    store_tile(0, xv, whv);
    __syncthreads();

    const int quad = lane >> 3, r8 = lane & 7;

    for (int kt = 0; kt < NTK; kt++) {
        const int b = kt & 1;

        if (kt + 1 < NTK) {
            const int k0 = (kt + 1) * BK;
#pragma unroll
            for (int i = 0; i < 8; i++) {
                int lin = i * THREADS + tid;
                int row = lin >> 3, c4 = lin & 7;
                xv[i] = *(const float4*)(x + (size_t)(m0 + row) * K_DIM + k0 + c4 * 4);
            }
            whv[0] = ((const uint2*)g_whi)[(kt + 1) * 512 + tid];
            whv[1] = ((const uint2*)g_whi)[(kt + 1) * 512 + tid + 256];
        }

        const uint32_t aH = sb + A_HI_OFF + b * A_BUF;
        const uint32_t wH = sb + W_HI_OFF + b * W_BUF;

#pragma unroll
        for (int kk = 0; kk < 2; kk++) {
            unsigned bh[8];
            const int nB = wn * 32 + ((quad >> 1) << 3) + r8;
            const int kB = kk * 16 + ((quad & 1) << 3);
#pragma unroll
            for (int s = 0; s < 2; s++) {
                uint32_t off = (uint32_t)(nB + s * 16) * A_ROW + kB * 2;
                LDMX4(&bh[s * 4], wH + off);
            }
            const int kA = kk * 16 + ((quad >> 1) << 3);
#pragma unroll
            for (int i = 0; i < 4; i++) {
                unsigned ah[4];
                const int mA = wm * 64 + i * 16 + ((quad & 1) << 3) + r8;
                uint32_t off = (uint32_t)mA * A_ROW + kA * 2;
                LDMX4(ah, aH + off);
#pragma unroll
                for (int j = 0; j < 4; j++)
                    MMA16816(c[i][j], ah, bh[2 * j], bh[2 * j + 1]);
            }
        }

        if (kt + 1 < NTK) store_tile(b ^ 1, xv, whv);
        __syncthreads();
    }

    // ---- write C fragments to smem [256][65] f32 ----
    float* cs = (float*)(smem + A_HI_OFF);
    const int g = lane >> 2, tg = lane & 3;
#pragma unroll
    for (int i = 0; i < 4; i++)
#pragma unroll
        for (int j = 0; j < 4; j++) {
            int row = wm * 64 + i * 16 + g;
            int col = wn * 32 + j * 8 + tg * 2;
            cs[row * 65 + col]           = c[i][j][0];
            cs[row * 65 + col + 1]       = c[i][j][1];
            cs[(row + 8) * 65 + col]     = c[i][j][2];
            cs[(row + 8) * 65 + col + 1] = c[i][j][3];
        }
    __syncthreads();

    // ---- per-token stats (one token per thread) ----
    const float* biass = (const float*)(smem + SM_BIAS);
    const int token = m0 + tid;
    const int tag = (g_tag_stride == 2) ? tagw[2 * token] : tagw[token];
    const float* row = cs + tid * 65;

    float mv = -3.4e38f; int mi = 0;
    float sl = 0.0f, st = 0.0f;
#pragma unroll
    for (int cc = 0; cc < T_DIM; cc++) {
        float vv = row[cc] + biass[cc];
        sl += vv;
        if (vv > mv) { mv = vv; mi = cc; }
        if (cc == tag) st = vv;
    }
    float se = 0.0f;
    float m2 = -3.4e38f;
#pragma unroll
    for (int cc = 0; cc < T_DIM; cc++) {
        float vv = row[cc] + biass[cc];
        se += expf(vv - mv);
        if (cc != mi && vv > m2) m2 = vv;
    }

    // ---- loss (bf16-accuracy logits; unbiased rounding -> rel err ~1e-6) ----
    const float E1 = 2.718281828459045f;
    float LSE = mv + logf(se);
    int   traw = *tptr;
    float tf = (traw > -1000000 && traw < 1000000) ? (float)traw : __int_as_float(traw);
    float s  = powf(tts[tag], tf);
    float es = expf(s);
    float Z  = 63.0f * E1 + es;
    float thr_loss  = LSE - ((E1 / Z) * (sl - st) + (es / Z) * st);
    int   thr_valid = (tag < (T_DIM - 3)) ? 1 : 0;
    int   thr_right = (thr_valid && (mi == tag)) ? 1 : 0;

    // ---- emit near-tie tokens to rescue worklist (no recompute here) ----
    if (mv - m2 < RESCUE_THR) {
        int ncand = 0; unsigned p0 = 0, p1 = 0;
#pragma unroll
        for (int cc = 0; cc < T_DIM; cc++) {
            float vv = row[cc] + biass[cc];
            if (vv >= mv - RESCUE_THR && ncand < 8) {
                if (ncand < 4) p0 |= (unsigned)cc << (8 * ncand);
                else           p1 |= (unsigned)cc << (8 * (ncand - 4));
                ncand++;
            }
        }
        unsigned slot = atomicAdd(&g_nwork, 1u);
        int meta = ncand | (tag << 4) | (thr_right << 12) | (thr_valid << 13);
        g_work[slot] = make_int4(token, meta, (int)p0, (int)p1);
    }

    // ---- deterministic block reduction (8 warps) -> partials ----
    float* s_loss  = (float*)(smem + SM_REDF);
    int*   s_right = (int*)(smem + SM_REDR);
    int*   s_valid = (int*)(smem + SM_REDV);
#pragma unroll
    for (int off = 16; off > 0; off >>= 1) {
        thr_loss  += __shfl_xor_sync(0xffffffffu, thr_loss,  off);
        thr_right += __shfl_xor_sync(0xffffffffu, thr_right, off);
        thr_valid += __shfl_xor_sync(0xffffffffu, thr_valid, off);
    }
    if (lane == 0) { s_loss[wid] = thr_loss; s_right[wid] = thr_right; s_valid[wid] = thr_valid; }
    __syncthreads();
    if (tid == 0) {
        float L = 0.0f; int R = 0, V = 0;
        for (int w = 0; w < 8; w++) { L += s_loss[w]; R += s_right[w]; V += s_valid[w]; }
        g_part_loss[blockIdx.x]  = L;
        g_part_right[blockIdx.x] = R;
        g_part_valid[blockIdx.x] = V;
    }
}

// ---------------- rescue: exact fp32 argmax via W^T (coalesced) + finalize ----------------
__global__ __launch_bounds__(256, 1)
void rescue_kernel(const float* __restrict__ x,
                   const float* __restrict__ bias,
                   float* __restrict__ out)
{
    __shared__ float s_loss[8];
    __shared__ int   s_right[8];
    __shared__ int   s_valid[8];
    __shared__ int   s_last;

    const int tid  = threadIdx.x;
    const int wid  = tid >> 5;
    const int lane = tid & 31;
    const unsigned nwork = g_nwork;
    const int gw = blockIdx.x * 8 + wid;          // global warp id (0..1023)

    for (unsigned e = gw; e < nwork; e += RGRID * 8) {
        int4 ent = g_work[e];
        const int token = ent.x;
        const int nc    = ent.y & 15;
        const int tag   = (ent.y >> 4) & 63;
        const int oldr  = (ent.y >> 12) & 1;
        const int valid = (ent.y >> 13) & 1;
        const unsigned q0 = (unsigned)ent.z, q1 = (unsigned)ent.w;

        const float4* xr4 = (const float4*)(x + (size_t)token * K_DIM);
        float acc[8];
#pragma unroll
        for (int j = 0; j < 8; j++) acc[j] = 0.0f;
        // per-candidate coalesced float4 dot; x row stays L1-hot across candidates
        for (int j = 0; j < nc; j++) {
            int cj = (int)((j < 4 ? (q0 >> (8 * j)) : (q1 >> (8 * (j - 4)))) & 0xffu);
            const float4* wt4 = (const float4*)(g_wt + (size_t)cj * K_DIM);
            float a = 0.0f;
#pragma unroll
            for (int i = 0; i < K_DIM / 128; i++) {      // 12 iters
                float4 xf = xr4[lane + 32 * i];
                float4 wf = wt4[lane + 32 * i];
                a += xf.x * wf.x + xf.y * wf.y + xf.z * wf.z + xf.w * wf.w;
            }
            acc[j] = a;
        }
#pragma unroll
        for (int j = 0; j < 8; j++)
#pragma unroll
            for (int off = 16; off > 0; off >>= 1)
                acc[j] += __shfl_xor_sync(0xffffffffu, acc[j], off);

        if (lane == 0 && valid) {
            // candidates ascending -> strict '>' keeps smallest-index tie-break
            float bmv = -3.4e38f; int bmi = 0;
            for (int j = 0; j < nc; j++) {
                int cj = (int)((j < 4 ? (q0 >> (8 * j)) : (q1 >> (8 * (j - 4)))) & 0xffu);
                float vv = acc[j] + bias[cj];
                if (vv > bmv) { bmv = vv; bmi = cj; }
            }
            int corr = (bmi == tag ? 1 : 0) - oldr;
            if (corr) atomicAdd(&g_right_corr, corr);
        }
    }

    // ---- completion + finalize in last CTA ----
    __syncthreads();
    if (tid == 0) {
        __threadfence();
        unsigned prev = atomicAdd(&g_done2, 1u);
        s_last = (prev == RGRID - 1) ? 1 : 0;
    }
    __syncthreads();
    if (s_last) {
        __threadfence();
        float L = 0.0f; int R = 0, V = 0;
        if (tid < GRID) {                          // GRID == 128
            L = g_part_loss[tid];
            R = g_part_right[tid];
            V = g_part_valid[tid];
        }
#pragma unroll
        for (int off = 16; off > 0; off >>= 1) {
            L += __shfl_xor_sync(0xffffffffu, L, off);
            R += __shfl_xor_sync(0xffffffffu, R, off);
            V += __shfl_xor_sync(0xffffffffu, V, off);
        }
        if (lane == 0) { s_loss[wid] = L; s_right[wid] = R; s_valid[wid] = V; }
        __syncthreads();
        if (tid == 0) {
            double LT = 0.0; long long RT = 0, VT = 0;
            for (int w = 0; w < 4; w++) {
                LT += (double)s_loss[w]; RT += s_right[w]; VT += s_valid[w];
            }
            RT += g_right_corr;
            out[0] = (float)LT;
            out[1] = (float)((double)RT / (double)VT);
            // reset counters for next graph replay
            g_right_corr = 0;
            atomicExch(&g_nwork, 0u);
            atomicExch(&g_done2, 0u);
        }
    }
}

extern "C" void kernel_launch(void* const* d_in, const int* in_sizes, int n_in,
                              void* d_out, int out_size) {
    const float* x    = (const float*)d_in[0];
    const float* W    = (const float*)d_in[1];
    const float* b    = (const float*)d_in[2];
    const int*   tagw = (const int*)d_in[3];   // raw 32-bit view, dtype detected on device
    // d_in[4] = attention_mask: uniform additive shift over tag dim -> provably a no-op
    const float* tts  = (const float*)d_in[5];
    const int*   tptr = (const int*)d_in[6];

    static int smem_set = 0;
    if (!smem_set) {
        cudaFuncSetAttribute(fused_gemm_loss_kernel,
                             cudaFuncAttributeMaxDynamicSharedMemorySize, SMEM_TOTAL);
        smem_set = 1;
    }

    prep_kernel<<<NTK, 256>>>(W, tagw);
    fused_gemm_loss_kernel<<<GRID, THREADS, SMEM_TOTAL>>>(x, b, tagw, tts, tptr);
    rescue_kernel<<<RGRID, 256>>>(x, b, (float*)d_out);
}

// round 15
// speedup vs baseline: 2.4814x; 1.2141x over previous
#include <cuda_runtime.h>
#include <cstdint>

// ---------------- problem constants ----------------
#define M_TOTAL 32768          // B*L tokens
#define K_DIM   1536           // H2
#define T_DIM   64             // tags
#define BM      256            // tokens per CTA
#define BK      64             // K per tile
#define NTK     (K_DIM / BK)   // 24 k-tiles
#define GRID    (M_TOTAL / BM) // 128 CTAs
#define THREADS 256            // 8 warps, each owns 32 rows x 64 cols
#define RESCUE_THR 0.03f       // ~16 sigma of 1-term bf16 logit error
#define RGRID   128            // rescue kernel CTAs

// ---------------- dynamic SMEM layout ----------------
// [0, 196608): W bf16 tiles, 24 x (64 rows x 128B), XOR-swizzled
// C overlay [256][65] f32 at offset 0 after GEMM (66560 B)
#define B_TILE_BYTES 8192
#define SM_BIAS   196608
#define SM_REDF   (196608 + 256)
#define SM_REDR   (196608 + 288)
#define SM_REDV   (196608 + 320)
#define SMEM_TOTAL (196608 + 512)

// ---------------- device scratch (no allocs allowed) ----------------
__device__ float    g_part_loss[GRID];
__device__ int      g_part_right[GRID];
__device__ int      g_part_valid[GRID];
__device__ int      g_tag_stride;
__device__ unsigned g_nwork;             // worklist size (reset by rescue last CTA)
__device__ unsigned g_done2;             // rescue completion counter
__device__ int      g_right_corr;        // argmax corrections (summed ints)
__device__ int4     g_work[M_TOTAL];     // worklist entries
__device__ uint4    g_wb[NTK * 512];     // W bf16 swizzled smem image (192KB)
__device__ float    g_wt[T_DIM * K_DIM]; // fp32 W transpose [tag][k] for rescue

// ---------------- helpers ----------------
__device__ __forceinline__ uint32_t smem_u32(const void* p) {
    uint32_t a;
    asm("{ .reg .u64 t; cvta.to.shared.u64 t, %1; cvt.u32.u64 %0, t; }" : "=r"(a) : "l"(p));
    return a;
}
__device__ __forceinline__ unsigned cvt_bf16x2(float a, float b) {
    // result: lo16 = bf16(a), hi16 = bf16(b)
    unsigned r;
    asm("cvt.rn.bf16x2.f32 %0, %1, %2;" : "=r"(r) : "f"(b), "f"(a));
    return r;
}

#define LDMX4(r, addr)                                                          \
    asm volatile("ldmatrix.sync.aligned.m8n8.x4.shared.b16 {%0,%1,%2,%3}, [%4];"\
                 : "=r"((r)[0]), "=r"((r)[1]), "=r"((r)[2]), "=r"((r)[3])       \
                 : "r"(addr))

#define MMA16816(c, a, b0, b1)                                                  \
    asm volatile("mma.sync.aligned.m16n8k16.row.col.f32.bf16.bf16.f32 "         \
                 "{%0,%1,%2,%3}, {%4,%5,%6,%7}, {%8,%9}, {%0,%1,%2,%3};"        \
                 : "+f"((c)[0]), "+f"((c)[1]), "+f"((c)[2]), "+f"((c)[3])       \
                 : "r"((a)[0]), "r"((a)[1]), "r"((a)[2]), "r"((a)[3]),          \
                   "r"(b0), "r"(b1))

// ---------------- prep: W -> swizzled bf16 image + fp32 transpose + tag detect ----------------
__global__ void prep_kernel(const float* __restrict__ W,
                            const int* __restrict__ tagw) {
    if (blockIdx.x == 0 && threadIdx.x < 32) {
        int l = threadIdx.x;
        int nz = 0;
#pragma unroll
        for (int i = 0; i < 4; i++) nz |= tagw[2 * (l + 32 * i) + 1];
        unsigned ball = __ballot_sync(0xffffffffu, nz != 0);
        if (l == 0) g_tag_stride = ball ? 1 : 2;
    }

    const int kt = blockIdx.x;        // 0..23
    const int t  = threadIdx.x;       // 256 threads
    const int n  = t >> 2;            // tag row 0..63
#pragma unroll
    for (int uu = 0; uu < 2; uu++) {
        int u = (t & 3) * 2 + uu;     // 16B unit 0..7 (8 bf16 k-values)
        float v[8];
#pragma unroll
        for (int e = 0; e < 8; e++) {
            int k = kt * BK + u * 8 + e;
            v[e] = W[(size_t)k * T_DIM + n];
            g_wt[(size_t)n * K_DIM + k] = v[e];
        }
        uint4 pk;
        pk.x = cvt_bf16x2(v[0], v[1]);
        pk.y = cvt_bf16x2(v[2], v[3]);
        pk.z = cvt_bf16x2(v[4], v[5]);
        pk.w = cvt_bf16x2(v[6], v[7]);
        g_wb[kt * 512 + n * 8 + (u ^ (n & 7))] = pk;   // XOR swizzle
    }
}

// ---------------- fused GEMM (A direct-from-gmem, no barriers) + loss + emit ----------------
__global__ __launch_bounds__(THREADS, 1)
void fused_gemm_loss_kernel(const float* __restrict__ x,
                            const float* __restrict__ bias,
                            const int*   __restrict__ tagw,
                            const float* __restrict__ tts,
                            const int*   __restrict__ tptr)
{
    extern __shared__ char smem[];
    const uint32_t sb  = smem_u32(smem);
    const int tid  = threadIdx.x;
    const int w    = tid >> 5;
    const int lane = tid & 31;
    const int g    = lane >> 2;       // 0..7
    const int tg   = lane & 3;        // 0..3
    const int quad = lane >> 3;       // 0..3
    const int r8   = lane & 7;
    const int m0   = blockIdx.x * BM;

    // ---- preload ALL W tiles into smem (flat copy of pre-swizzled image) ----
    {
        uint4* bs = (uint4*)smem;
#pragma unroll
        for (int i = 0; i < NTK * 512 / THREADS; i++)     // 48 iters
            bs[i * THREADS + tid] = g_wb[i * THREADS + tid];
    }
    if (tid < T_DIM) ((float*)(smem + SM_BIAS))[tid] = bias[tid];
    __syncthreads();                  // the ONLY pre-loop barrier

    float c[2][8][4];
#pragma unroll
    for (int i = 0; i < 2; i++)
#pragma unroll
        for (int j = 0; j < 8; j++)
#pragma unroll
            for (int q = 0; q < 4; q++) c[i][j][q] = 0.0f;

    // A fragment base pointers: warp owns rows m0+32w .. +31
    const float* xr0 = x + (size_t)(m0 + w * 32 + g) * K_DIM + 2 * tg;
    const float* xr1 = xr0 + 8 * K_DIM;                  // row g+8

    // in-flight fp32 fragment buffer: pf[fi = kk*2+i][4 pairs]
    float2 pf[8][4];
#pragma unroll
    for (int kk = 0; kk < 4; kk++)
#pragma unroll
        for (int i = 0; i < 2; i++) {
            int o = i * 16 * K_DIM + kk * 16;
            pf[kk * 2 + i][0] = *(const float2*)(xr0 + o);
            pf[kk * 2 + i][1] = *(const float2*)(xr1 + o);
            pf[kk * 2 + i][2] = *(const float2*)(xr0 + o + 8);
            pf[kk * 2 + i][3] = *(const float2*)(xr1 + o + 8);
        }

    for (int kt = 0; kt < NTK; kt++) {
        const uint32_t bbase = sb + kt * B_TILE_BYTES;
#pragma unroll
        for (int kk = 0; kk < 4; kk++) {
            // B fragments for this k16 chunk: n=64 via 4 LDSM.x4 (swizzled rows)
            unsigned bh[16];
#pragma unroll
            for (int s = 0; s < 4; s++) {
                int row = s * 16 + ((quad >> 1) << 3) + r8;
                int u   = 2 * kk + (quad & 1);
                uint32_t addr = bbase + row * 128 + ((u ^ (row & 7)) << 4);
                LDMX4(&bh[s * 4], addr);
            }
#pragma unroll
            for (int i = 0; i < 2; i++) {
                const int fi = kk * 2 + i;
                unsigned a[4];
                a[0] = cvt_bf16x2(pf[fi][0].x, pf[fi][0].y);   // row g,   k lo
                a[1] = cvt_bf16x2(pf[fi][1].x, pf[fi][1].y);   // row g+8, k lo
                a[2] = cvt_bf16x2(pf[fi][2].x, pf[fi][2].y);   // row g,   k hi
                a[3] = cvt_bf16x2(pf[fi][3].x, pf[fi][3].y);   // row g+8, k hi
                if (kt < NTK - 1) {                            // prefetch next tile, same frag
                    int o = i * 16 * K_DIM + (kt + 1) * BK + kk * 16;
                    pf[fi][0] = *(const float2*)(xr0 + o);
                    pf[fi][1] = *(const float2*)(xr1 + o);
                    pf[fi][2] = *(const float2*)(xr0 + o + 8);
                    pf[fi][3] = *(const float2*)(xr1 + o + 8);
                }
#pragma unroll
                for (int j = 0; j < 8; j++)
                    MMA16816(c[i][j], a,
                             bh[(j >> 1) * 4 + (j & 1) * 2],
                             bh[(j >> 1) * 4 + (j & 1) * 2 + 1]);
            }
        }
    }

    // ---- C -> smem overlay [256][65] (overwrites W region; all reads done) ----
    __syncthreads();
    float* cs = (float*)smem;
#pragma unroll
    for (int i = 0; i < 2; i++)
#pragma unroll
        for (int j = 0; j < 8; j++) {
            int row = w * 32 + i * 16 + g;
            int col = j * 8 + tg * 2;
            cs[row * 65 + col]           = c[i][j][0];
            cs[row * 65 + col + 1]       = c[i][j][1];
            cs[(row + 8) * 65 + col]     = c[i][j][2];
            cs[(row + 8) * 65 + col + 1] = c[i][j][3];
        }
    __syncthreads();

    // ---- per-token stats (one token per thread) ----
    const float* biass = (const float*)(smem + SM_BIAS);
    const int token = m0 + tid;
    const int tag = (g_tag_stride == 2) ? tagw[2 * token] : tagw[token];
    const float* row = cs + tid * 65;

    float mv = -3.4e38f; int mi = 0;
    float sl = 0.0f, st = 0.0f;
#pragma unroll
    for (int cc = 0; cc < T_DIM; cc++) {
        float vv = row[cc] + biass[cc];
        sl += vv;
        if (vv > mv) { mv = vv; mi = cc; }
        if (cc == tag) st = vv;
    }
    float se = 0.0f, m2 = -3.4e38f;
#pragma unroll
    for (int cc = 0; cc < T_DIM; cc++) {
        float vv = row[cc] + biass[cc];
        se += expf(vv - mv);
        if (cc != mi && vv > m2) m2 = vv;
    }

    // ---- loss (bf16-accuracy logits; unbiased rounding -> rel err ~1e-6) ----
    const float E1 = 2.718281828459045f;
    float LSE = mv + logf(se);
    int   traw = *tptr;
    float tf = (traw > -1000000 && traw < 1000000) ? (float)traw : __int_as_float(traw);
    float s  = powf(tts[tag], tf);
    float es = expf(s);
    float Z  = 63.0f * E1 + es;
    float thr_loss  = LSE - ((E1 / Z) * (sl - st) + (es / Z) * st);
    int   thr_valid = (tag < (T_DIM - 3)) ? 1 : 0;
    int   thr_right = (thr_valid && (mi == tag)) ? 1 : 0;

    // ---- emit near-tie tokens to rescue worklist ----
    if (mv - m2 < RESCUE_THR) {
        int ncand = 0; unsigned p0 = 0, p1 = 0;
#pragma unroll
        for (int cc = 0; cc < T_DIM; cc++) {
            float vv = row[cc] + biass[cc];
            if (vv >= mv - RESCUE_THR && ncand < 8) {
                if (ncand < 4) p0 |= (unsigned)cc << (8 * ncand);
                else           p1 |= (unsigned)cc << (8 * (ncand - 4));
                ncand++;
            }
        }
        unsigned slot = atomicAdd(&g_nwork, 1u);
        int meta = ncand | (tag << 4) | (thr_right << 12) | (thr_valid << 13);
        g_work[slot] = make_int4(token, meta, (int)p0, (int)p1);
    }

    // ---- deterministic block reduction (8 warps) -> partials ----
    float* s_loss  = (float*)(smem + SM_REDF);
    int*   s_right = (int*)(smem + SM_REDR);
    int*   s_valid = (int*)(smem + SM_REDV);
#pragma unroll
    for (int off = 16; off > 0; off >>= 1) {
        thr_loss  += __shfl_xor_sync(0xffffffffu, thr_loss,  off);
        thr_right += __shfl_xor_sync(0xffffffffu, thr_right, off);
        thr_valid += __shfl_xor_sync(0xffffffffu, thr_valid, off);
    }
    if (lane == 0) { s_loss[w] = thr_loss; s_right[w] = thr_right; s_valid[w] = thr_valid; }
    __syncthreads();
    if (tid == 0) {
        float L = 0.0f; int R = 0, V = 0;
        for (int ww = 0; ww < 8; ww++) { L += s_loss[ww]; R += s_right[ww]; V += s_valid[ww]; }
        g_part_loss[blockIdx.x]  = L;
        g_part_right[blockIdx.x] = R;
        g_part_valid[blockIdx.x] = V;
    }
}

// ---------------- rescue: exact fp32 argmax via W^T (coalesced) + finalize ----------------
__global__ __launch_bounds__(256, 1)
void rescue_kernel(const float* __restrict__ x,
                   const float* __restrict__ bias,
                   float* __restrict__ out)
{
    __shared__ float s_loss[8];
    __shared__ int   s_right[8];
    __shared__ int   s_valid[8];
    __shared__ int   s_last;

    const int tid  = threadIdx.x;
    const int wid  = tid >> 5;
    const int lane = tid & 31;
    const unsigned nwork = g_nwork;
    const int gw = blockIdx.x * 8 + wid;

    for (unsigned e = gw; e < nwork; e += RGRID * 8) {
        int4 ent = g_work[e];
        const int token = ent.x;
        const int nc    = ent.y & 15;
        const int tag   = (ent.y >> 4) & 63;
        const int oldr  = (ent.y >> 12) & 1;
        const int valid = (ent.y >> 13) & 1;
        const unsigned q0 = (unsigned)ent.z, q1 = (unsigned)ent.w;

        const float4* xr4 = (const float4*)(x + (size_t)token * K_DIM);
        float acc[8];
#pragma unroll
        for (int j = 0; j < 8; j++) acc[j] = 0.0f;
        for (int j = 0; j < nc; j++) {
            int cj = (int)((j < 4 ? (q0 >> (8 * j)) : (q1 >> (8 * (j - 4)))) & 0xffu);
            const float4* wt4 = (const float4*)(g_wt + (size_t)cj * K_DIM);
            float a = 0.0f;
#pragma unroll
            for (int i = 0; i < K_DIM / 128; i++) {
                float4 xf = xr4[lane + 32 * i];
                float4 wf = wt4[lane + 32 * i];
                a += xf.x * wf.x + xf.y * wf.y + xf.z * wf.z + xf.w * wf.w;
            }
            acc[j] = a;
        }
#pragma unroll
        for (int j = 0; j < 8; j++)
#pragma unroll
            for (int off = 16; off > 0; off >>= 1)
                acc[j] += __shfl_xor_sync(0xffffffffu, acc[j], off);

        if (lane == 0 && valid) {
            float bmv = -3.4e38f; int bmi = 0;
            for (int j = 0; j < nc; j++) {
                int cj = (int)((j < 4 ? (q0 >> (8 * j)) : (q1 >> (8 * (j - 4)))) & 0xffu);
                float vv = acc[j] + bias[cj];
                if (vv > bmv) { bmv = vv; bmi = cj; }
            }
            int corr = (bmi == tag ? 1 : 0) - oldr;
            if (corr) atomicAdd(&g_right_corr, corr);
        }
    }

    __syncthreads();
    if (tid == 0) {
        __threadfence();
        unsigned prev = atomicAdd(&g_done2, 1u);
        s_last = (prev == RGRID - 1) ? 1 : 0;
    }
    __syncthreads();
    if (s_last) {
        __threadfence();
        float L = 0.0f; int R = 0, V = 0;
        if (tid < GRID) {
            L = g_part_loss[tid];
            R = g_part_right[tid];
            V = g_part_valid[tid];
        }
#pragma unroll
        for (int off = 16; off > 0; off >>= 1) {
            L += __shfl_xor_sync(0xffffffffu, L, off);
            R += __shfl_xor_sync(0xffffffffu, R, off);
            V += __shfl_xor_sync(0xffffffffu, V, off);
        }
        if (lane == 0) { s_loss[wid] = L; s_right[wid] = R; s_valid[wid] = V; }
        __syncthreads();
        if (tid == 0) {
            double LT = 0.0; long long RT = 0, VT = 0;
            for (int ww = 0; ww < 4; ww++) {
                LT += (double)s_loss[ww]; RT += s_right[ww]; VT += s_valid[ww];
            }
            RT += g_right_corr;
            out[0] = (float)LT;
            out[1] = (float)((double)RT / (double)VT);
            g_right_corr = 0;
            atomicExch(&g_nwork, 0u);
            atomicExch(&g_done2, 0u);
        }
    }
}

extern "C" void kernel_launch(void* const* d_in, const int* in_sizes, int n_in,
                              void* d_out, int out_size) {
    const float* x    = (const float*)d_in[0];
    const float* W    = (const float*)d_in[1];
    const float* b    = (const float*)d_in[2];
    const int*   tagw = (const int*)d_in[3];   // raw 32-bit view, dtype detected on device
    // d_in[4] = attention_mask: uniform additive shift over tag dim -> provably a no-op
    const float* tts  = (const float*)d_in[5];
    const int*   tptr = (const int*)d_in[6];

    static int smem_set = 0;
    if (!smem_set) {
        cudaFuncSetAttribute(fused_gemm_loss_kernel,
                             cudaFuncAttributeMaxDynamicSharedMemorySize, SMEM_TOTAL);
        smem_set = 1;
    }

    prep_kernel<<<NTK, 256>>>(W, tagw);
    fused_gemm_loss_kernel<<<GRID, THREADS, SMEM_TOTAL>>>(x, b, tagw, tts, tptr);
    rescue_kernel<<<RGRID, 256>>>(x, b, (float*)d_out);
}